// round 11
// baseline (speedup 1.0000x reference)
#include <cuda_runtime.h>

// HarmonicLowering: out[b, k*C+ch, f, t] = w*x[b,ch,idx,t] + (1-w)*x[b,ch,idx1,t]
//   prod=f*(k+1); idx=prod>>2; w=1-(prod&3)*0.25
//   w<1 implies idx<=191 so idx+1 needs no clamp; w==1 -> alias idx1=idx.
// Pair trick: consecutive t4 positions share (b,ch,f,k) -> same idx & w,
// so each thread processes 2 consecutive float4 (32B) with 256-bit ld/st.
// B=8, C=32, F=256, T=512, K=4.

#define BATCH 8
#define CH    32
#define FREQ  256
#define TIME  512

#define T4     (TIME / 4)                      // 128 float4 per row
#define P4     (T4 / 2)                        // 64 pairs per row
#define PAIRS  (BATCH * 4 * CH * FREQ * P4)    // 16,777,216 output pairs
#define PPT    2                               // pairs per thread

__device__ __forceinline__ void ldg256(const float4* p, float4& lo, float4& hi)
{
    unsigned r0,r1,r2,r3,r4,r5,r6,r7;
    asm("ld.global.nc.v8.b32 {%0,%1,%2,%3,%4,%5,%6,%7}, [%8];"
        : "=r"(r0),"=r"(r1),"=r"(r2),"=r"(r3),
          "=r"(r4),"=r"(r5),"=r"(r6),"=r"(r7)
        : "l"(p));
    lo.x=__uint_as_float(r0); lo.y=__uint_as_float(r1);
    lo.z=__uint_as_float(r2); lo.w=__uint_as_float(r3);
    hi.x=__uint_as_float(r4); hi.y=__uint_as_float(r5);
    hi.z=__uint_as_float(r6); hi.w=__uint_as_float(r7);
}

__device__ __forceinline__ void stg256_cs(float4* p, const float4& lo, const float4& hi)
{
    asm volatile("st.global.cs.v8.b32 [%0], {%1,%2,%3,%4,%5,%6,%7,%8};"
        :: "l"(p),
           "r"(__float_as_uint(lo.x)),"r"(__float_as_uint(lo.y)),
           "r"(__float_as_uint(lo.z)),"r"(__float_as_uint(lo.w)),
           "r"(__float_as_uint(hi.x)),"r"(__float_as_uint(hi.y)),
           "r"(__float_as_uint(hi.z)),"r"(__float_as_uint(hi.w))
        : "memory");
}

__global__ __launch_bounds__(256)
void harmonic_lowering_kernel(const float4* __restrict__ x, float4* __restrict__ out)
{
    const unsigned int pbase = blockIdx.x * (256u * PPT) + threadIdx.x;

    unsigned int off0[PPT], off1[PPT];
    float        w[PPT];

    #pragma unroll
    for (int j = 0; j < PPT; j++) {
        unsigned int p  = pbase + j * 256u;
        unsigned int tp = p & (P4 - 1);            // pair-in-row  [0:6)
        unsigned int f  = (p >> 6) & (FREQ - 1);   // [6:14)
        unsigned int kc = (p >> 14) & 127u;        // [14:21)  k*32+ch
        unsigned int b  = p >> 21;                 // [21:24)
        unsigned int prod = f * ((kc >> 5) + 1u);
        unsigned int frac = prod & 3u;
        unsigned int idx  = prod >> 2;
        unsigned int idx1 = frac ? (idx + 1u) : idx;
        w[j] = 1.0f - (float)frac * 0.25f;
        unsigned int base = ((b * CH + (kc & 31u)) * FREQ) * T4 + 2u * tp;
        off0[j] = base + idx  * T4;                // even float4 idx -> 32B aligned
        off1[j] = base + idx1 * T4;
    }

    // front-batched: 4 independent 256-bit loads (128B in flight per thread)
    float4 g0lo[PPT], g0hi[PPT], g1lo[PPT], g1hi[PPT];
    #pragma unroll
    for (int j = 0; j < PPT; j++) ldg256(&x[off0[j]], g0lo[j], g0hi[j]);
    #pragma unroll
    for (int j = 0; j < PPT; j++) ldg256(&x[off1[j]], g1lo[j], g1hi[j]);

    #pragma unroll
    for (int j = 0; j < PPT; j++) {
        float4 rlo, rhi;
        rlo.x = fmaf(w[j], g0lo[j].x - g1lo[j].x, g1lo[j].x);
        rlo.y = fmaf(w[j], g0lo[j].y - g1lo[j].y, g1lo[j].y);
        rlo.z = fmaf(w[j], g0lo[j].z - g1lo[j].z, g1lo[j].z);
        rlo.w = fmaf(w[j], g0lo[j].w - g1lo[j].w, g1lo[j].w);
        rhi.x = fmaf(w[j], g0hi[j].x - g1hi[j].x, g1hi[j].x);
        rhi.y = fmaf(w[j], g0hi[j].y - g1hi[j].y, g1hi[j].y);
        rhi.z = fmaf(w[j], g0hi[j].z - g1hi[j].z, g1hi[j].z);
        rhi.w = fmaf(w[j], g0hi[j].w - g1hi[j].w, g1hi[j].w);
        unsigned int p = pbase + j * 256u;
        stg256_cs(&out[2u * p], rlo, rhi);         // 32B-aligned streaming store
    }
}

extern "C" void kernel_launch(void* const* d_in, const int* in_sizes, int n_in,
                              void* d_out, int out_size)
{
    (void)in_sizes; (void)n_in; (void)out_size;
    const float4* x = (const float4*)d_in[0];
    float4* out = (float4*)d_out;

    const int threads = 256;
    const int blocks  = PAIRS / (threads * PPT);   // 32768, exact
    harmonic_lowering_kernel<<<blocks, threads>>>(x, out);
}

// round 12
// speedup vs baseline: 1.2505x; 1.2505x over previous
#include <cuda_runtime.h>

// HarmonicLowering: out[b, k*C+ch, f, t] = w * x[b,ch,idx,t] + (1-w) * x[b,ch,idx1,t]
//   prod = f*(k+1); idx = prod>>2; w = 1 - (prod&3)*0.25
//   w<1 implies idx<=191 so idx+1 needs no clamp; w==1 -> alias idx1=idx
//   (same-address load, L1 hit, result unaffected).
// B=8, C=32, F=256, T=512, K=4. All powers of two -> shift/mask decode.
// R12: default (L2-cached) stores instead of __stcs — let L2 buffer the
// write stream for better DRAM burst scheduling.

#define BATCH 8
#define CH    32
#define FREQ  256
#define TIME  512
#define KTAPS 4

#define T4       (TIME / 4)                          // 128 float4 per time-row
#define OUT_E4   (BATCH * KTAPS * CH * FREQ * T4)    // 33,554,432
#define VPT      4                                   // outputs per thread

__global__ __launch_bounds__(256)
void harmonic_lowering_kernel(const float4* __restrict__ x, float4* __restrict__ out)
{
    const unsigned int ibase = blockIdx.x * (256u * VPT) + threadIdx.x;

    unsigned int off0[VPT], off1[VPT];
    float        w[VPT];

    #pragma unroll
    for (int j = 0; j < VPT; j++) {
        unsigned int i  = ibase + j * 256u;
        unsigned int t4 = i & (T4 - 1);
        unsigned int f  = (i >> 7) & (FREQ - 1);
        unsigned int kc = (i >> 15) & 127u;
        unsigned int b  = i >> 22;
        unsigned int prod = f * ((kc >> 5) + 1u);
        unsigned int frac = prod & 3u;
        unsigned int idx  = prod >> 2;
        unsigned int idx1 = frac ? (idx + 1u) : idx;
        w[j] = 1.0f - (float)frac * 0.25f;
        unsigned int base = ((b * CH + (kc & 31u)) * FREQ) * T4 + t4;
        off0[j] = base + idx  * T4;
        off1[j] = base + idx1 * T4;
    }

    // front-batched: 8 independent LDG.128 in flight
    float4 g0[VPT], g1[VPT];
    #pragma unroll
    for (int j = 0; j < VPT; j++) g0[j] = x[off0[j]];
    #pragma unroll
    for (int j = 0; j < VPT; j++) g1[j] = x[off1[j]];

    #pragma unroll
    for (int j = 0; j < VPT; j++) {
        float4 r;
        r.x = fmaf(w[j], g0[j].x - g1[j].x, g1[j].x);
        r.y = fmaf(w[j], g0[j].y - g1[j].y, g1[j].y);
        r.z = fmaf(w[j], g0[j].z - g1[j].z, g1[j].z);
        r.w = fmaf(w[j], g0[j].w - g1[j].w, g1[j].w);
        out[ibase + j * 256u] = r;   // default policy: L2-buffered writeback
    }
}

extern "C" void kernel_launch(void* const* d_in, const int* in_sizes, int n_in,
                              void* d_out, int out_size)
{
    (void)in_sizes; (void)n_in; (void)out_size;
    const float4* x = (const float4*)d_in[0];
    float4* out = (float4*)d_out;

    const int threads = 256;
    const int blocks  = OUT_E4 / (threads * VPT);   // 32768, exact
    harmonic_lowering_kernel<<<blocks, threads>>>(x, out);
}

// round 13
// speedup vs baseline: 1.2528x; 1.0018x over previous
#include <cuda_runtime.h>

// HarmonicLowering: out[b, k*C+ch, f, t] = w * x[b,ch,idx,t] + (1-w) * x[b,ch,idx1,t]
//   prod = f*(k+1); idx = prod>>2; w = 1 - (prod&3)*0.25
//   w<1 implies idx<=191 so idx+1 needs no clamp.
//   frac==0 -> w==1 -> result is g0 exactly: SKIP the g1 load entirely.
//   frac is warp-uniform (warp spans only t4), so the branch never diverges.
// B=8, C=32, F=256, T=512, K=4. All powers of two -> shift/mask decode.

#define BATCH 8
#define CH    32
#define FREQ  256
#define TIME  512
#define KTAPS 4

#define T4       (TIME / 4)                          // 128 float4 per time-row
#define OUT_E4   (BATCH * KTAPS * CH * FREQ * T4)    // 33,554,432
#define VPT      4                                   // outputs per thread

__global__ __launch_bounds__(256)
void harmonic_lowering_kernel(const float4* __restrict__ x, float4* __restrict__ out)
{
    const unsigned int ibase = blockIdx.x * (256u * VPT) + threadIdx.x;

    unsigned int off0[VPT], off1[VPT], frac[VPT];
    float        w[VPT];

    #pragma unroll
    for (int j = 0; j < VPT; j++) {
        unsigned int i  = ibase + j * 256u;
        unsigned int t4 = i & (T4 - 1);
        unsigned int f  = (i >> 7) & (FREQ - 1);
        unsigned int kc = (i >> 15) & 127u;
        unsigned int b  = i >> 22;
        unsigned int prod = f * ((kc >> 5) + 1u);
        frac[j] = prod & 3u;
        unsigned int idx = prod >> 2;
        w[j] = 1.0f - (float)frac[j] * 0.25f;
        unsigned int base = ((b * CH + (kc & 31u)) * FREQ) * T4 + t4;
        off0[j] = base + idx * T4;
        off1[j] = off0[j] + T4;          // only consumed when frac!=0 (no clamp needed)
    }

    // front-batched primary loads: 4 independent LDG.128
    float4 g0[VPT];
    #pragma unroll
    for (int j = 0; j < VPT; j++) g0[j] = x[off0[j]];

    // secondary loads only where needed (warp-uniform predicate, ~50% skipped)
    float4 g1[VPT];
    #pragma unroll
    for (int j = 0; j < VPT; j++) {
        g1[j] = g0[j];
        if (frac[j]) g1[j] = x[off1[j]];
    }

    #pragma unroll
    for (int j = 0; j < VPT; j++) {
        float4 r;
        r.x = fmaf(w[j], g0[j].x - g1[j].x, g1[j].x);
        r.y = fmaf(w[j], g0[j].y - g1[j].y, g1[j].y);
        r.z = fmaf(w[j], g0[j].z - g1[j].z, g1[j].z);
        r.w = fmaf(w[j], g0[j].w - g1[j].w, g1[j].w);
        out[ibase + j * 256u] = r;       // default policy: L2-buffered writeback
    }
}

extern "C" void kernel_launch(void* const* d_in, const int* in_sizes, int n_in,
                              void* d_out, int out_size)
{
    (void)in_sizes; (void)n_in; (void)out_size;
    const float4* x = (const float4*)d_in[0];
    float4* out = (float4*)d_out;

    const int threads = 256;
    const int blocks  = OUT_E4 / (threads * VPT);   // 32768, exact
    harmonic_lowering_kernel<<<blocks, threads>>>(x, out);
}